// round 11
// baseline (speedup 1.0000x reference)
#include <cuda_runtime.h>
#include <cuda_bf16.h>
#include <cstdint>
#include <math.h>

#define NDIM 512
#define C 128
#define NN (NDIM*NDIM)
#define PLANE NN
#define WFB 67584          // 128 x 132 f32 weight array bytes
#define XFB 33792          // 64 x 132 f32 activation array bytes

// ---------------------------------------------------------------------------
// scratch
// ---------------------------------------------------------------------------
__device__ __align__(16) float g_i[(size_t)C*NN];     // tf32-rounded, channel-major
__device__ __align__(16) float g_j[(size_t)C*NN];
__device__ __align__(16) float g_ecm[(size_t)C*NN];
__device__ __align__(16) float g_sg [(size_t)NN*C];
__device__ __align__(16) float g_wf[6 * 128 * 128];   // tf32 [n][k]: Wis Wi Wjs Wj Ws Wp

extern __shared__ char smem_[];

// ---------------------------------------------------------------------------
// PTX helpers
// ---------------------------------------------------------------------------
__device__ __forceinline__ uint32_t smem_u32(const void* p) {
    uint32_t a;
    asm("{ .reg .u64 t; cvta.to.shared.u64 t, %1; cvt.u32.u64 %0, t; }" : "=r"(a) : "l"(p));
    return a;
}
__device__ __forceinline__ void ldm_x4(uint32_t addr, uint32_t* r) {
    asm volatile("ldmatrix.sync.aligned.m8n8.x4.shared.b16 {%0,%1,%2,%3}, [%4];"
        : "=r"(r[0]), "=r"(r[1]), "=r"(r[2]), "=r"(r[3]) : "r"(addr));
}
__device__ __forceinline__ void mma_tf32(float* d, const uint32_t* a, uint32_t b0, uint32_t b1) {
    asm volatile("mma.sync.aligned.m16n8k8.row.col.f32.tf32.tf32.f32 "
        "{%0,%1,%2,%3}, {%4,%5,%6,%7}, {%8,%9}, {%0,%1,%2,%3};"
        : "+f"(d[0]), "+f"(d[1]), "+f"(d[2]), "+f"(d[3])
        : "r"(a[0]), "r"(a[1]), "r"(a[2]), "r"(a[3]), "r"(b0), "r"(b1));
}
__device__ __forceinline__ void cp16(uint32_t dst, const void* src) {
    asm volatile("cp.async.cg.shared.global [%0], [%1], 16;" :: "r"(dst), "l"(src) : "memory");
}
#define CP_COMMIT() asm volatile("cp.async.commit_group;" ::: "memory")
#define CP_WAIT(n)  asm volatile("cp.async.wait_group %0;" :: "n"(n) : "memory")
__device__ __forceinline__ float sigmoidf_(float x) { return 1.0f / (1.0f + __expf(-x)); }
__device__ __forceinline__ float tf32r(float x) {
    float r;
    asm("cvt.rna.tf32.f32 %0, %1;" : "=f"(r) : "f"(x));
    return r;
}

// ---------------------------------------------------------------------------
// Prologue: transpose + tf32-round weights
// ---------------------------------------------------------------------------
__global__ void convert_w_kernel(const float* __restrict__ Wis, const float* __restrict__ Wi,
                                 const float* __restrict__ Wjs, const float* __restrict__ Wj,
                                 const float* __restrict__ Ws,  const float* __restrict__ Wp) {
    const float* src[6] = {Wis, Wi, Wjs, Wj, Ws, Wp};
    const float* W = src[blockIdx.x];
    float* outp = g_wf + (size_t)blockIdx.x * 16384;
    for (int idx = threadIdx.x; idx < 16384; idx += blockDim.x) {
        int n = idx >> 7, k = idx & 127;
        outp[n * 128 + k] = tf32r(W[k * 128 + n]);
    }
}

// cp.async one tf32 weight [128 n][132 f32 stride] into smem, 256 threads
__device__ __forceinline__ void loadWf(int m, uint32_t sW, int tid) {
    const char* src = (const char*)g_wf + (size_t)m * 65536;
    #pragma unroll
    for (int it = 0; it < 16; ++it) {
        int idx = tid + it * 256;
        int row = idx >> 5, ch = idx & 31;
        cp16(sW + row * 528 + ch * 16, src + row * 512 + ch * 16);
    }
}

// ---------------------------------------------------------------------------
// tf32 warp GEMM: 32x32 warp tile, K=128, row stride 528 B
// 8 warps: wm=w>>2 (2, rows), wn=w&3 (4, cols) -> 64x128 block tile
// acc[(ma*4+na)*4+q]: q=0:(g,t2) 1:(g,t2+1) 2:(g+8,t2) 3:(g+8,t2+1)
// ---------------------------------------------------------------------------
__device__ __forceinline__ void wgemm_t32(uint32_t sA, uint32_t sB,
                                          int lane, int wm, int wn, float* acc) {
    int lr = lane & 7, sel = lane >> 3;
    uint32_t aRow = (uint32_t)((wm*32 + (sel & 1)*8 + lr) * 528 + (sel >> 1)*16);
    uint32_t bRow = (uint32_t)((wn*32 + (sel & 1)*8 + lr) * 528 + (sel >> 1)*16);
    #pragma unroll
    for (int kk = 0; kk < 16; ++kk) {
        uint32_t a[2][4];
        #pragma unroll
        for (int ma = 0; ma < 2; ++ma)
            ldm_x4(sA + aRow + (uint32_t)(ma * 16 * 528 + kk * 32), a[ma]);
        #pragma unroll
        for (int p = 0; p < 2; ++p) {
            uint32_t b[4];
            ldm_x4(sB + bRow + (uint32_t)(p * 16 * 528 + kk * 32), b);
            #pragma unroll
            for (int ma = 0; ma < 2; ++ma) {
                mma_tf32(acc + (ma*4 + p*2 + 0)*4, a[ma], b[0], b[2]);
                mma_tf32(acc + (ma*4 + p*2 + 1)*4, a[ma], b[1], b[3]);
            }
        }
    }
}

// ---------------------------------------------------------------------------
// Stage 1: LN + 5 GEMMs. 256 threads, 64-row tiles, 2 CTAs/SM.
// smem: Xf 64x132 f32 (33792) | W 128x132 f32 (67584) = 101376 B
// ---------------------------------------------------------------------------
__global__ void __launch_bounds__(256, 2)
stage1_kernel(const float* __restrict__ x2d, const float* __restrict__ mask,
              const float* __restrict__ ga1, const float* __restrict__ be1,
              const float* __restrict__ bi,  const float* __restrict__ bis,
              const float* __restrict__ bj,  const float* __restrict__ bjs,
              const float* __restrict__ bs) {
    float* Xf = (float*)smem_;
    float* T  = (float*)(smem_ + XFB);     // W region; doubles as staging
    uint32_t sX = smem_u32(Xf);
    uint32_t sW = sX + XFB;

    int tid = threadIdx.x, lane = tid & 31, w = tid >> 5;
    int wm = w >> 2, wn = w & 3;
    int g = lane >> 2, t2 = (lane & 3) * 2;
    size_t rowbase = (size_t)blockIdx.x * 64;

    loadWf(0, sW, tid); CP_COMMIT();   // Wis

    // coalesced x2d read -> Xf raw (rows are 512B contiguous)
    #pragma unroll
    for (int it = 0; it < 8; ++it) {
        int idx = tid + it * 256;
        int r = idx >> 5, c4 = (idx & 31) << 2;
        float4 f = *(const float4*)(x2d + (rowbase + r) * C + c4);
        *(float4*)(Xf + r * 132 + c4) = f;
    }
    __syncthreads();

    // LN: warp per row (8 warps x 8 rows), lane owns c, c+32, c+64, c+96
    #pragma unroll 1
    for (int it = 0; it < 8; ++it) {
        int r = w + it * 8;
        float v[4], s = 0.f, ss = 0.f;
        #pragma unroll
        for (int q = 0; q < 4; ++q) {
            float x = Xf[r * 132 + lane + 32*q];
            v[q] = x; s += x; ss += x * x;
        }
        #pragma unroll
        for (int d = 16; d >= 1; d >>= 1) {
            s  += __shfl_xor_sync(0xffffffffu, s, d);
            ss += __shfl_xor_sync(0xffffffffu, ss, d);
        }
        float mu = s * (1.0f / C);
        float rs = rsqrtf(ss * (1.0f / C) - mu * mu + 1e-5f);
        #pragma unroll
        for (int q = 0; q < 4; ++q) {
            int k = lane + 32*q;
            Xf[r * 132 + k] = tf32r((v[q] - mu) * rs * __ldg(ga1 + k) + __ldg(be1 + k));
        }
    }

    float accg[32], accm[32];

    #pragma unroll 1
    for (int pass = 0; pass < 2; ++pass) {
        const float* bgp = pass ? bjs : bis;
        const float* bmp = pass ? bj  : bi;
        float* outp = pass ? g_j : g_i;

        // gate GEMM
        CP_WAIT(0);
        __syncthreads();
        #pragma unroll
        for (int q = 0; q < 32; ++q) accg[q] = 0.f;
        wgemm_t32(sX, sW, lane, wm, wn, accg);
        #pragma unroll
        for (int ma = 0; ma < 2; ++ma)
            #pragma unroll
            for (int na = 0; na < 4; ++na) {
                int idx = (ma*4 + na) * 4;
                int c0 = wn*32 + na*8 + t2;
                float b0 = __ldg(bgp + c0), b1 = __ldg(bgp + c0 + 1);
                accg[idx+0] = sigmoidf_(accg[idx+0] + b0);
                accg[idx+1] = sigmoidf_(accg[idx+1] + b1);
                accg[idx+2] = sigmoidf_(accg[idx+2] + b0);
                accg[idx+3] = sigmoidf_(accg[idx+3] + b1);
            }
        __syncthreads();                        // done reading W
        loadWf(2*pass + 1, sW, tid); CP_COMMIT();   // main weight

        // main GEMM
        CP_WAIT(0);
        __syncthreads();
        #pragma unroll
        for (int q = 0; q < 32; ++q) accm[q] = 0.f;
        wgemm_t32(sX, sW, lane, wm, wn, accm);
        __syncthreads();                        // done reading W -> staging

        // combine -> T[col][row] (stride 68)
        #pragma unroll
        for (int ma = 0; ma < 2; ++ma) {
            int r0 = wm*32 + ma*16 + g;
            float m0 = __ldg(mask + rowbase + r0);
            float m1 = __ldg(mask + rowbase + r0 + 8);
            #pragma unroll
            for (int na = 0; na < 4; ++na) {
                int idx = (ma*4 + na) * 4;
                int c0 = wn*32 + na*8 + t2;
                float b0 = __ldg(bmp + c0), b1 = __ldg(bmp + c0 + 1);
                T[(c0  )*68 + r0    ] = tf32r((accm[idx+0] + b0) * accg[idx+0] * m0);
                T[(c0+1)*68 + r0    ] = tf32r((accm[idx+1] + b1) * accg[idx+1] * m0);
                T[(c0  )*68 + r0 + 8] = tf32r((accm[idx+2] + b0) * accg[idx+2] * m1);
                T[(c0+1)*68 + r0 + 8] = tf32r((accm[idx+3] + b1) * accg[idx+3] * m1);
            }
        }
        __syncthreads();

        // channel-major flush (coalesced)
        {
            int cch = tid >> 1, q = tid & 1;
            const float4* src = (const float4*)(T + cch * 68 + q * 32);
            float4* dst = (float4*)(outp + (size_t)cch * PLANE + rowbase + q * 32);
            #pragma unroll
            for (int t = 0; t < 8; ++t) dst[t] = src[t];
        }
        __syncthreads();
        loadWf(pass == 0 ? 2 : 4, sW, tid); CP_COMMIT();   // next gate / Ws
    }

    // sg = sigmoid(x@Ws+bs): GEMM -> smem staging -> coalesced flush
    CP_WAIT(0);
    __syncthreads();
    #pragma unroll
    for (int q = 0; q < 32; ++q) accg[q] = 0.f;
    wgemm_t32(sX, sW, lane, wm, wn, accg);
    __syncthreads();                            // done reading W -> staging
    #pragma unroll
    for (int ma = 0; ma < 2; ++ma) {
        int r0 = wm*32 + ma*16 + g;
        #pragma unroll
        for (int na = 0; na < 4; ++na) {
            int idx = (ma*4 + na) * 4;
            int c0 = wn*32 + na*8 + t2;
            *(float2*)(T + (r0    )*132 + c0) = make_float2(accg[idx+0], accg[idx+1]);
            *(float2*)(T + (r0 + 8)*132 + c0) = make_float2(accg[idx+2], accg[idx+3]);
        }
    }
    __syncthreads();
    #pragma unroll
    for (int it = 0; it < 8; ++it) {
        int idx = tid + it * 256;
        int r = idx >> 5, c4 = (idx & 31) << 2;
        float4 v = *(const float4*)(T + r * 132 + c4);
        float4 b = *(const float4*)(bs + c4);
        float4 o;
        o.x = sigmoidf_(v.x + b.x); o.y = sigmoidf_(v.y + b.y);
        o.z = sigmoidf_(v.z + b.z); o.w = sigmoidf_(v.w + b.w);
        *(float4*)(g_sg + (rowbase + r) * C + c4) = o;
    }
}

// ---------------------------------------------------------------------------
// Stage 2: einsum, tf32, block 128x128, 256 threads, 2 CTAs/SM.
// stage: A 18432 + B 18432 = 36864; 2 stages = 73728 B; output staged in smem
// warp tile 32x64: wm=w>>1 (4, rows), wn=w&1 (2, cols)
// ---------------------------------------------------------------------------
#define ESTG 36864

__device__ __forceinline__ void e_load(uint32_t sdst,
                                       const char* pA, const char* pB,
                                       int kb, int tid) {
    #pragma unroll
    for (int it = 0; it < 4; ++it) {
        int idx = tid + it * 256;
        int row = idx >> 3, ch = idx & 7;
        cp16(sdst + row * 144 + ch * 16,
             pA + (size_t)row * 2048 + kb * 128 + ch * 16);
    }
    #pragma unroll
    for (int it = 0; it < 4; ++it) {
        int idx = tid + it * 256;
        int row = idx >> 3, ch = idx & 7;
        cp16(sdst + 18432 + row * 144 + ch * 16,
             pB + (size_t)row * 2048 + kb * 128 + ch * 16);
    }
}

__device__ __forceinline__ void e_mma(uint32_t st, int lane, int wm, int wn, float* acc) {
    int lr = lane & 7, sel = lane >> 3;
    uint32_t aRow = (uint32_t)((wm*32 + (sel & 1)*8 + lr) * 144 + (sel >> 1)*16);
    uint32_t bRow = (uint32_t)((wn*64 + (sel & 1)*8 + lr) * 144 + (sel >> 1)*16);
    uint32_t sA = st, sB = st + 18432;
    #pragma unroll
    for (int kk = 0; kk < 4; ++kk) {
        uint32_t a[2][4];
        #pragma unroll
        for (int ma = 0; ma < 2; ++ma)
            ldm_x4(sA + aRow + (uint32_t)(ma * 16 * 144 + kk * 32), a[ma]);
        #pragma unroll
        for (int p = 0; p < 4; ++p) {
            uint32_t b[4];
            ldm_x4(sB + bRow + (uint32_t)(p * 16 * 144 + kk * 32), b);
            #pragma unroll
            for (int ma = 0; ma < 2; ++ma) {
                mma_tf32(acc + (ma*8 + p*2 + 0)*4, a[ma], b[0], b[2]);
                mma_tf32(acc + (ma*8 + p*2 + 1)*4, a[ma], b[1], b[3]);
            }
        }
    }
}

__global__ void __launch_bounds__(256, 2)
einsum_kernel() {
    uint32_t sb = smem_u32(smem_);
    float* Of = (float*)smem_;                 // output staging [128 r][132]
    int tid = threadIdx.x, lane = tid & 31, w = tid >> 5;
    int wm = w >> 1, wn = w & 1;
    int g = lane >> 2, t2 = (lane & 3) * 2;
    int c = blockIdx.z;
    int ibase = blockIdx.x * 128, jbase = blockIdx.y * 128;

    const char* pA = (const char*)(g_i + (size_t)c * PLANE + (size_t)ibase * NDIM);
    const char* pB = (const char*)(g_j + (size_t)c * PLANE + (size_t)jbase * NDIM);

    float acc[64];
    #pragma unroll
    for (int q = 0; q < 64; ++q) acc[q] = 0.f;

    e_load(sb, pA, pB, 0, tid); CP_COMMIT();

    #pragma unroll 1
    for (int kb = 0; kb < 16; ++kb) {
        if (kb < 15) {
            e_load(sb + ((kb + 1) & 1) * ESTG, pA, pB, kb + 1, tid);
            CP_COMMIT();
            CP_WAIT(1);
        } else {
            CP_WAIT(0);
        }
        __syncthreads();
        e_mma(sb + (kb & 1) * ESTG, lane, wm, wn, acc);
        __syncthreads();
    }

    // stage output tile in smem, then coalesced flush
    #pragma unroll
    for (int ma = 0; ma < 2; ++ma) {
        int r0 = wm*32 + ma*16 + g;
        #pragma unroll
        for (int na = 0; na < 8; ++na) {
            int idx = (ma*8 + na) * 4;
            int c0 = wn*64 + na*8 + t2;
            *(float2*)(Of + (r0    )*132 + c0) = make_float2(acc[idx+0], acc[idx+1]);
            *(float2*)(Of + (r0 + 8)*132 + c0) = make_float2(acc[idx+2], acc[idx+3]);
        }
    }
    __syncthreads();

    float* O = g_ecm + (size_t)c * PLANE;
    #pragma unroll
    for (int it = 0; it < 16; ++it) {
        int idx = tid + it * 256;
        int r = idx >> 5, c4 = (idx & 31) << 2;
        *(float4*)(O + (size_t)(ibase + r) * NDIM + jbase + c4) =
            *(const float4*)(Of + r * 132 + c4);
    }
}

// ---------------------------------------------------------------------------
// Stage 3: 64-row tiles, 256 threads, 2 CTAs/SM, fully coalesced.
// smem: XT 64x132 (33792) | W region 67584 (gather staging / W / out staging)
// ---------------------------------------------------------------------------
__global__ void __launch_bounds__(256, 2)
stage3_kernel(const float* __restrict__ mask,
              const float* __restrict__ ga2, const float* __restrict__ be2,
              const float* __restrict__ bp,  float* __restrict__ out) {
    float* XT = (float*)smem_;
    float* S  = (float*)(smem_ + XFB);       // W region: gather staging [128 c][65]
    uint32_t sXT = smem_u32(XT);
    uint32_t sW  = sXT + XFB;

    int tid = threadIdx.x, lane = tid & 31, w = tid >> 5;
    int wm = w >> 2, wn = w & 3;
    int g = lane >> 2, t2 = (lane & 3) * 2;
    size_t rowbase = (size_t)blockIdx.x * 64;

    // coalesced gather: g_ecm[c][rowbase..+64] -> S[c][r] (stride 65, scalar STS)
    #pragma unroll
    for (int it = 0; it < 8; ++it) {
        int idx = tid + it * 256;
        int c = idx >> 4, rq = (idx & 15) << 2;
        float4 f = *(const float4*)(g_ecm + (size_t)c * PLANE + rowbase + rq);
        S[c * 65 + rq + 0] = f.x;
        S[c * 65 + rq + 1] = f.y;
        S[c * 65 + rq + 2] = f.z;
        S[c * 65 + rq + 3] = f.w;
    }
    __syncthreads();

    // LN: warp per row (8 warps x 8 rows), conflict-free strided smem reads
    #pragma unroll 1
    for (int it = 0; it < 8; ++it) {
        int r = w + it * 8;
        float v[4], s = 0.f, ss = 0.f;
        #pragma unroll
        for (int q = 0; q < 4; ++q) {
            float x = S[(lane + 32*q) * 65 + r];
            v[q] = x; s += x; ss += x * x;
        }
        #pragma unroll
        for (int d = 16; d >= 1; d >>= 1) {
            s  += __shfl_xor_sync(0xffffffffu, s, d);
            ss += __shfl_xor_sync(0xffffffffu, ss, d);
        }
        float mu = s * (1.0f / C);
        float rs = rsqrtf(ss * (1.0f / C) - mu * mu + 1e-5f);
        #pragma unroll
        for (int q = 0; q < 4; ++q) {
            int k = lane + 32*q;
            XT[r * 132 + k] = tf32r((v[q] - mu) * rs * __ldg(ga2 + k) + __ldg(be2 + k));
        }
    }
    __syncthreads();                 // S no longer needed

    loadWf(5, sW, tid);
    CP_COMMIT();
    CP_WAIT(0);
    __syncthreads();

    float acc[32];
    #pragma unroll
    for (int q = 0; q < 32; ++q) acc[q] = 0.f;
    wgemm_t32(sXT, sW, lane, wm, wn, acc);
    __syncthreads();                 // done reading W -> out staging

    float* Tout = S;                 // [64 r][132]
    #pragma unroll
    for (int ma = 0; ma < 2; ++ma) {
        int r0 = wm*32 + ma*16 + g;
        #pragma unroll
        for (int na = 0; na < 4; ++na) {
            int idx = (ma*4 + na) * 4;
            int c0 = wn*32 + na*8 + t2;
            *(float2*)(Tout + (r0    )*132 + c0) = make_float2(acc[idx+0], acc[idx+1]);
            *(float2*)(Tout + (r0 + 8)*132 + c0) = make_float2(acc[idx+2], acc[idx+3]);
        }
    }
    __syncthreads();

    // fused coalesced flush: (acc + bp) * sg * mask -> out
    #pragma unroll
    for (int it = 0; it < 8; ++it) {
        int idx = tid + it * 256;
        int r = idx >> 5, c4 = (idx & 31) << 2;
        float4 v = *(const float4*)(Tout + r * 132 + c4);
        float4 b = *(const float4*)(bp + c4);
        float4 sgv = *(const float4*)(g_sg + (rowbase + r) * C + c4);
        float m = __ldg(mask + rowbase + r);
        float4 o;
        o.x = (v.x + b.x) * sgv.x * m;
        o.y = (v.y + b.y) * sgv.y * m;
        o.z = (v.z + b.z) * sgv.z * m;
        o.w = (v.w + b.w) * sgv.w * m;
        *(float4*)(out + (rowbase + r) * C + c4) = o;
    }
}

// ---------------------------------------------------------------------------
extern "C" void kernel_launch(void* const* d_in, const int* in_sizes, int n_in,
                              void* d_out, int out_size) {
    const float* x2d  = (const float*)d_in[0];
    const float* mask = (const float*)d_in[1];
    const float* ga1  = (const float*)d_in[2];
    const float* be1  = (const float*)d_in[3];
    const float* ga2  = (const float*)d_in[4];
    const float* be2  = (const float*)d_in[5];
    const float* Wi   = (const float*)d_in[6];
    const float* bi   = (const float*)d_in[7];
    const float* Wis  = (const float*)d_in[8];
    const float* bis  = (const float*)d_in[9];
    const float* Wj   = (const float*)d_in[10];
    const float* bj   = (const float*)d_in[11];
    const float* Wjs  = (const float*)d_in[12];
    const float* bjs  = (const float*)d_in[13];
    const float* Wp   = (const float*)d_in[14];
    const float* bp   = (const float*)d_in[15];
    const float* Ws   = (const float*)d_in[16];
    const float* bs   = (const float*)d_in[17];

    const int smem_s1 = XFB + WFB;     // 101376
    const int smem_e  = 2 * ESTG;      // 73728
    const int smem_s3 = XFB + WFB;     // 101376
    cudaFuncSetAttribute(stage1_kernel, cudaFuncAttributeMaxDynamicSharedMemorySize, smem_s1);
    cudaFuncSetAttribute(einsum_kernel, cudaFuncAttributeMaxDynamicSharedMemorySize, smem_e);
    cudaFuncSetAttribute(stage3_kernel, cudaFuncAttributeMaxDynamicSharedMemorySize, smem_s3);

    convert_w_kernel<<<6, 256>>>(Wis, Wi, Wjs, Wj, Ws, Wp);

    stage1_kernel<<<NN / 64, 256, smem_s1>>>(x2d, mask, ga1, be1,
                                             bi, bis, bj, bjs, bs);

    dim3 grid2(NDIM / 128, NDIM / 128, C);
    einsum_kernel<<<grid2, 256, smem_e>>>();

    stage3_kernel<<<NN / 64, 256, smem_s3>>>(mask, ga2, be2, bp, (float*)d_out);
}

// round 12
// speedup vs baseline: 1.4727x; 1.4727x over previous
#include <cuda_runtime.h>
#include <cuda_bf16.h>
#include <cstdint>
#include <math.h>

#define NDIM 512
#define C 128
#define NN (NDIM*NDIM)
#define PLANE NN
#define WFB 67584          // 128 x 132 f32 weight array bytes
#define XFB 33792          // 64 x 132 f32 activation array bytes

// ---------------------------------------------------------------------------
// scratch
// ---------------------------------------------------------------------------
__device__ __align__(16) float g_i[(size_t)C*NN];     // tf32-rounded, channel-major
__device__ __align__(16) float g_j[(size_t)C*NN];
__device__ __align__(16) float g_ecm[(size_t)C*NN];
__device__ __align__(16) float g_sg [(size_t)NN*C];
__device__ __align__(16) float g_wf[6 * 128 * 128];   // tf32 [n][k]: Wis Wi Wjs Wj Ws Wp

extern __shared__ char smem_[];

// ---------------------------------------------------------------------------
// PTX helpers
// ---------------------------------------------------------------------------
__device__ __forceinline__ uint32_t smem_u32(const void* p) {
    uint32_t a;
    asm("{ .reg .u64 t; cvta.to.shared.u64 t, %1; cvt.u32.u64 %0, t; }" : "=r"(a) : "l"(p));
    return a;
}
__device__ __forceinline__ void ldm_x4(uint32_t addr, uint32_t* r) {
    asm volatile("ldmatrix.sync.aligned.m8n8.x4.shared.b16 {%0,%1,%2,%3}, [%4];"
        : "=r"(r[0]), "=r"(r[1]), "=r"(r[2]), "=r"(r[3]) : "r"(addr));
}
__device__ __forceinline__ void mma_tf32(float* d, const uint32_t* a, uint32_t b0, uint32_t b1) {
    asm volatile("mma.sync.aligned.m16n8k8.row.col.f32.tf32.tf32.f32 "
        "{%0,%1,%2,%3}, {%4,%5,%6,%7}, {%8,%9}, {%0,%1,%2,%3};"
        : "+f"(d[0]), "+f"(d[1]), "+f"(d[2]), "+f"(d[3])
        : "r"(a[0]), "r"(a[1]), "r"(a[2]), "r"(a[3]), "r"(b0), "r"(b1));
}
__device__ __forceinline__ void cp16(uint32_t dst, const void* src) {
    asm volatile("cp.async.cg.shared.global [%0], [%1], 16;" :: "r"(dst), "l"(src) : "memory");
}
#define CP_COMMIT() asm volatile("cp.async.commit_group;" ::: "memory")
#define CP_WAIT(n)  asm volatile("cp.async.wait_group %0;" :: "n"(n) : "memory")
__device__ __forceinline__ float sigmoidf_(float x) { return 1.0f / (1.0f + __expf(-x)); }
__device__ __forceinline__ float tf32r(float x) {
    float r;
    asm("cvt.rna.tf32.f32 %0, %1;" : "=f"(r) : "f"(x));
    return r;
}

// ---------------------------------------------------------------------------
// Prologue: transpose + tf32-round weights
// ---------------------------------------------------------------------------
__global__ void convert_w_kernel(const float* __restrict__ Wis, const float* __restrict__ Wi,
                                 const float* __restrict__ Wjs, const float* __restrict__ Wj,
                                 const float* __restrict__ Ws,  const float* __restrict__ Wp) {
    const float* src[6] = {Wis, Wi, Wjs, Wj, Ws, Wp};
    const float* W = src[blockIdx.x];
    float* outp = g_wf + (size_t)blockIdx.x * 16384;
    for (int idx = threadIdx.x; idx < 16384; idx += blockDim.x) {
        int n = idx >> 7, k = idx & 127;
        outp[n * 128 + k] = tf32r(W[k * 128 + n]);
    }
}

// cp.async one tf32 weight [128 n][132 f32 stride] into smem, 256 threads
__device__ __forceinline__ void loadWf(int m, uint32_t sW, int tid) {
    const char* src = (const char*)g_wf + (size_t)m * 65536;
    #pragma unroll
    for (int it = 0; it < 16; ++it) {
        int idx = tid + it * 256;
        int row = idx >> 5, ch = idx & 31;
        cp16(sW + row * 528 + ch * 16, src + row * 512 + ch * 16);
    }
}

// ---------------------------------------------------------------------------
// tf32 warp GEMM: 32x32 warp tile, K=128, row stride 528 B
// 8 warps: wm=w>>2 (2, rows), wn=w&3 (4, cols) -> 64x128 block tile
// acc[(ma*4+na)*4+q]: q=0:(g,t2) 1:(g,t2+1) 2:(g+8,t2) 3:(g+8,t2+1)
// ---------------------------------------------------------------------------
__device__ __forceinline__ void wgemm_t32(uint32_t sA, uint32_t sB,
                                          int lane, int wm, int wn, float* acc) {
    int lr = lane & 7, sel = lane >> 3;
    uint32_t aRow = (uint32_t)((wm*32 + (sel & 1)*8 + lr) * 528 + (sel >> 1)*16);
    uint32_t bRow = (uint32_t)((wn*32 + (sel & 1)*8 + lr) * 528 + (sel >> 1)*16);
    #pragma unroll
    for (int kk = 0; kk < 16; ++kk) {
        uint32_t a[2][4];
        #pragma unroll
        for (int ma = 0; ma < 2; ++ma)
            ldm_x4(sA + aRow + (uint32_t)(ma * 16 * 528 + kk * 32), a[ma]);
        #pragma unroll
        for (int p = 0; p < 2; ++p) {
            uint32_t b[4];
            ldm_x4(sB + bRow + (uint32_t)(p * 16 * 528 + kk * 32), b);
            #pragma unroll
            for (int ma = 0; ma < 2; ++ma) {
                mma_tf32(acc + (ma*4 + p*2 + 0)*4, a[ma], b[0], b[2]);
                mma_tf32(acc + (ma*4 + p*2 + 1)*4, a[ma], b[1], b[3]);
            }
        }
    }
}

// ---------------------------------------------------------------------------
// Stage 1: LN + 5 GEMMs. 256 threads, 64-row tiles, 2 CTAs/SM. (R10)
// smem: Xf 64x132 f32 (33792) | W 128x132 f32 (67584) = 101376 B
// ---------------------------------------------------------------------------
__global__ void __launch_bounds__(256, 2)
stage1_kernel(const float* __restrict__ x2d, const float* __restrict__ mask,
              const float* __restrict__ ga1, const float* __restrict__ be1,
              const float* __restrict__ bi,  const float* __restrict__ bis,
              const float* __restrict__ bj,  const float* __restrict__ bjs,
              const float* __restrict__ bs) {
    float* Xf = (float*)smem_;
    float* T  = (float*)(smem_ + XFB);     // W region; doubles as staging
    uint32_t sX = smem_u32(Xf);
    uint32_t sW = sX + XFB;

    int tid = threadIdx.x, lane = tid & 31, w = tid >> 5;
    int wm = w >> 2, wn = w & 3;
    int g = lane >> 2, t2 = (lane & 3) * 2;
    size_t rowbase = (size_t)blockIdx.x * 64;

    loadWf(0, sW, tid); CP_COMMIT();   // Wis

    // layernorm: 4 threads/row, 32 channels each
    {
        int r = tid >> 2, e = tid & 3;
        const float* xr = x2d + (rowbase + r) * C + e * 32;
        float v[32], s = 0.f, ss = 0.f;
        #pragma unroll
        for (int t = 0; t < 8; ++t) {
            float4 f = *(const float4*)(xr + t * 4);
            v[4*t+0]=f.x; v[4*t+1]=f.y; v[4*t+2]=f.z; v[4*t+3]=f.w;
            s += f.x + f.y + f.z + f.w;
            ss += f.x*f.x + f.y*f.y + f.z*f.z + f.w*f.w;
        }
        s  += __shfl_xor_sync(0xffffffffu, s, 1);
        s  += __shfl_xor_sync(0xffffffffu, s, 2);
        ss += __shfl_xor_sync(0xffffffffu, ss, 1);
        ss += __shfl_xor_sync(0xffffffffu, ss, 2);
        float mu = s * (1.0f / C);
        float rs = rsqrtf(ss * (1.0f / C) - mu * mu + 1e-5f);
        #pragma unroll
        for (int t = 0; t < 32; ++t) {
            int k = e * 32 + t;
            Xf[r * 132 + k] = tf32r((v[t] - mu) * rs * __ldg(ga1 + k) + __ldg(be1 + k));
        }
    }

    float accg[32], accm[32];

    #pragma unroll 1
    for (int pass = 0; pass < 2; ++pass) {
        const float* bgp = pass ? bjs : bis;
        const float* bmp = pass ? bj  : bi;
        float* outp = pass ? g_j : g_i;

        // gate GEMM
        CP_WAIT(0);
        __syncthreads();
        #pragma unroll
        for (int q = 0; q < 32; ++q) accg[q] = 0.f;
        wgemm_t32(sX, sW, lane, wm, wn, accg);
        #pragma unroll
        for (int ma = 0; ma < 2; ++ma)
            #pragma unroll
            for (int na = 0; na < 4; ++na) {
                int idx = (ma*4 + na) * 4;
                int c0 = wn*32 + na*8 + t2;
                float b0 = __ldg(bgp + c0), b1 = __ldg(bgp + c0 + 1);
                accg[idx+0] = sigmoidf_(accg[idx+0] + b0);
                accg[idx+1] = sigmoidf_(accg[idx+1] + b1);
                accg[idx+2] = sigmoidf_(accg[idx+2] + b0);
                accg[idx+3] = sigmoidf_(accg[idx+3] + b1);
            }
        __syncthreads();                        // done reading W
        loadWf(2*pass + 1, sW, tid); CP_COMMIT();   // main weight

        // main GEMM
        CP_WAIT(0);
        __syncthreads();
        #pragma unroll
        for (int q = 0; q < 32; ++q) accm[q] = 0.f;
        wgemm_t32(sX, sW, lane, wm, wn, accm);
        __syncthreads();                        // done reading W -> staging

        // combine -> T[col][row] (stride 68)
        #pragma unroll
        for (int ma = 0; ma < 2; ++ma) {
            int r0 = wm*32 + ma*16 + g;
            float m0 = __ldg(mask + rowbase + r0);
            float m1 = __ldg(mask + rowbase + r0 + 8);
            #pragma unroll
            for (int na = 0; na < 4; ++na) {
                int idx = (ma*4 + na) * 4;
                int c0 = wn*32 + na*8 + t2;
                float b0 = __ldg(bmp + c0), b1 = __ldg(bmp + c0 + 1);
                T[(c0  )*68 + r0    ] = tf32r((accm[idx+0] + b0) * accg[idx+0] * m0);
                T[(c0+1)*68 + r0    ] = tf32r((accm[idx+1] + b1) * accg[idx+1] * m0);
                T[(c0  )*68 + r0 + 8] = tf32r((accm[idx+2] + b0) * accg[idx+2] * m1);
                T[(c0+1)*68 + r0 + 8] = tf32r((accm[idx+3] + b1) * accg[idx+3] * m1);
            }
        }
        __syncthreads();

        // channel-major flush (coalesced)
        {
            int cch = tid >> 1, q = tid & 1;
            const float4* src = (const float4*)(T + cch * 68 + q * 32);
            float4* dst = (float4*)(outp + (size_t)cch * PLANE + rowbase + q * 32);
            #pragma unroll
            for (int t = 0; t < 8; ++t) dst[t] = src[t];
        }
        __syncthreads();
        loadWf(pass == 0 ? 2 : 4, sW, tid); CP_COMMIT();   // next gate / Ws
    }

    // sg = sigmoid(x@Ws+bs)
    CP_WAIT(0);
    __syncthreads();
    #pragma unroll
    for (int q = 0; q < 32; ++q) accg[q] = 0.f;
    wgemm_t32(sX, sW, lane, wm, wn, accg);
    #pragma unroll
    for (int ma = 0; ma < 2; ++ma) {
        size_t r0 = rowbase + wm*32 + ma*16 + g;
        #pragma unroll
        for (int na = 0; na < 4; ++na) {
            int idx = (ma*4 + na) * 4;
            int c0 = wn*32 + na*8 + t2;
            float b0 = __ldg(bs + c0), b1 = __ldg(bs + c0 + 1);
            *(float2*)(g_sg + r0 * C + c0) =
                make_float2(sigmoidf_(accg[idx+0] + b0), sigmoidf_(accg[idx+1] + b1));
            *(float2*)(g_sg + (r0 + 8) * C + c0) =
                make_float2(sigmoidf_(accg[idx+2] + b0), sigmoidf_(accg[idx+3] + b1));
        }
    }
}

// ---------------------------------------------------------------------------
// Stage 2: einsum, tf32, block 128x128, 256 threads, 2 CTAs/SM.
// 3-stage cp.async pipeline, ONE barrier per k-chunk.
// stage: A 18432 + B 18432 = 36864 B; 3 stages = 110592 B
// ---------------------------------------------------------------------------
#define ESTG 36864

__device__ __forceinline__ void e_load(uint32_t sdst,
                                       const char* pA, const char* pB,
                                       int kb, int tid) {
    #pragma unroll
    for (int it = 0; it < 4; ++it) {
        int idx = tid + it * 256;
        int row = idx >> 3, ch = idx & 7;
        cp16(sdst + row * 144 + ch * 16,
             pA + (size_t)row * 2048 + kb * 128 + ch * 16);
    }
    #pragma unroll
    for (int it = 0; it < 4; ++it) {
        int idx = tid + it * 256;
        int row = idx >> 3, ch = idx & 7;
        cp16(sdst + 18432 + row * 144 + ch * 16,
             pB + (size_t)row * 2048 + kb * 128 + ch * 16);
    }
}

__device__ __forceinline__ void e_mma(uint32_t st, int lane, int wm, int wn, float* acc) {
    int lr = lane & 7, sel = lane >> 3;
    uint32_t aRow = (uint32_t)((wm*32 + (sel & 1)*8 + lr) * 144 + (sel >> 1)*16);
    uint32_t bRow = (uint32_t)((wn*64 + (sel & 1)*8 + lr) * 144 + (sel >> 1)*16);
    uint32_t sA = st, sB = st + 18432;
    #pragma unroll
    for (int kk = 0; kk < 4; ++kk) {
        uint32_t a[2][4];
        #pragma unroll
        for (int ma = 0; ma < 2; ++ma)
            ldm_x4(sA + aRow + (uint32_t)(ma * 16 * 144 + kk * 32), a[ma]);
        #pragma unroll
        for (int p = 0; p < 4; ++p) {
            uint32_t b[4];
            ldm_x4(sB + bRow + (uint32_t)(p * 16 * 144 + kk * 32), b);
            #pragma unroll
            for (int ma = 0; ma < 2; ++ma) {
                mma_tf32(acc + (ma*8 + p*2 + 0)*4, a[ma], b[0], b[2]);
                mma_tf32(acc + (ma*8 + p*2 + 1)*4, a[ma], b[1], b[3]);
            }
        }
    }
}

__global__ void __launch_bounds__(256, 2)
einsum_kernel() {
    uint32_t sb = smem_u32(smem_);
    int tid = threadIdx.x, lane = tid & 31, w = tid >> 5;
    int wm = w >> 1, wn = w & 1;
    int g = lane >> 2, t2 = (lane & 3) * 2;
    int c = blockIdx.z;
    int ibase = blockIdx.x * 128, jbase = blockIdx.y * 128;

    const char* pA = (const char*)(g_i + (size_t)c * PLANE + (size_t)ibase * NDIM);
    const char* pB = (const char*)(g_j + (size_t)c * PLANE + (size_t)jbase * NDIM);

    float acc[64];
    #pragma unroll
    for (int q = 0; q < 64; ++q) acc[q] = 0.f;

    e_load(sb,        pA, pB, 0, tid); CP_COMMIT();
    e_load(sb + ESTG, pA, pB, 1, tid); CP_COMMIT();

    #pragma unroll 1
    for (int kb = 0; kb < 16; ++kb) {
        if (kb < 15) { CP_WAIT(1); } else { CP_WAIT(0); }
        __syncthreads();
        if (kb + 2 < 16) {
            e_load(sb + ((kb + 2) % 3) * ESTG, pA, pB, kb + 2, tid);
            CP_COMMIT();
        }
        e_mma(sb + (kb % 3) * ESTG, lane, wm, wn, acc);
    }

    float* O = g_ecm + (size_t)c * PLANE;
    #pragma unroll
    for (int ma = 0; ma < 2; ++ma) {
        size_t r0 = (size_t)(ibase + wm*32 + ma*16 + g);
        #pragma unroll
        for (int na = 0; na < 8; ++na) {
            int idx = (ma*8 + na) * 4;
            int c0 = jbase + wn*64 + na*8 + t2;
            *(float2*)(O + r0 * NDIM + c0)       = make_float2(acc[idx+0], acc[idx+1]);
            *(float2*)(O + (r0 + 8) * NDIM + c0) = make_float2(acc[idx+2], acc[idx+3]);
        }
    }
}

// ---------------------------------------------------------------------------
// Stage 3: 64-row tiles, 256 threads, 2 CTAs/SM. (R10)
// smem: XT 64x132 f32 (33792) | W (67584) = 101376 B
// ---------------------------------------------------------------------------
__global__ void __launch_bounds__(256, 2)
stage3_kernel(const float* __restrict__ mask,
              const float* __restrict__ ga2, const float* __restrict__ be2,
              const float* __restrict__ bp,  float* __restrict__ out) {
    float* XT = (float*)smem_;
    uint32_t sXT = smem_u32(XT);
    uint32_t sW  = sXT + XFB;

    int tid = threadIdx.x, lane = tid & 31, w = tid >> 5;
    int wm = w >> 2, wn = w & 3;
    int g = lane >> 2, t2 = (lane & 3) * 2;
    size_t rowbase = (size_t)blockIdx.x * 64;

    loadWf(5, sW, tid);
    CP_COMMIT();

    // gather channel-major einsum output + LN over channels
    {
        int r = tid >> 2, e = tid & 3;
        const float* base = g_ecm + (size_t)(e * 32) * PLANE + rowbase + r;
        float v[32], s = 0.f, ss = 0.f;
        #pragma unroll
        for (int t = 0; t < 32; ++t) {
            float x = __ldg(base + (size_t)t * PLANE);
            v[t] = x; s += x; ss += x * x;
        }
        s  += __shfl_xor_sync(0xffffffffu, s, 1);
        s  += __shfl_xor_sync(0xffffffffu, s, 2);
        ss += __shfl_xor_sync(0xffffffffu, ss, 1);
        ss += __shfl_xor_sync(0xffffffffu, ss, 2);
        float mu = s * (1.0f / C);
        float rs = rsqrtf(ss * (1.0f / C) - mu * mu + 1e-5f);
        #pragma unroll
        for (int t = 0; t < 32; ++t) {
            int k = e * 32 + t;
            XT[r * 132 + k] = tf32r((v[t] - mu) * rs * __ldg(ga2 + k) + __ldg(be2 + k));
        }
    }
    CP_WAIT(0);
    __syncthreads();

    float acc[32];
    #pragma unroll
    for (int q = 0; q < 32; ++q) acc[q] = 0.f;
    wgemm_t32(sXT, sW, lane, wm, wn, acc);

    #pragma unroll
    for (int ma = 0; ma < 2; ++ma) {
        size_t r0 = rowbase + wm*32 + ma*16 + g;
        float m0 = __ldg(mask + r0);
        float m1 = __ldg(mask + r0 + 8);
        #pragma unroll
        for (int na = 0; na < 4; ++na) {
            int idx = (ma*4 + na) * 4;
            int c0 = wn*32 + na*8 + t2;
            float b0 = __ldg(bp + c0), b1 = __ldg(bp + c0 + 1);
            float2 s0 = *(const float2*)(g_sg + r0 * C + c0);
            float2 s1 = *(const float2*)(g_sg + (r0 + 8) * C + c0);
            *(float2*)(out + r0 * C + c0) =
                make_float2((acc[idx+0] + b0) * s0.x * m0, (acc[idx+1] + b1) * s0.y * m0);
            *(float2*)(out + (r0 + 8) * C + c0) =
                make_float2((acc[idx+2] + b0) * s1.x * m1, (acc[idx+3] + b1) * s1.y * m1);
        }
    }
}

// ---------------------------------------------------------------------------
extern "C" void kernel_launch(void* const* d_in, const int* in_sizes, int n_in,
                              void* d_out, int out_size) {
    const float* x2d  = (const float*)d_in[0];
    const float* mask = (const float*)d_in[1];
    const float* ga1  = (const float*)d_in[2];
    const float* be1  = (const float*)d_in[3];
    const float* ga2  = (const float*)d_in[4];
    const float* be2  = (const float*)d_in[5];
    const float* Wi   = (const float*)d_in[6];
    const float* bi   = (const float*)d_in[7];
    const float* Wis  = (const float*)d_in[8];
    const float* bis  = (const float*)d_in[9];
    const float* Wj   = (const float*)d_in[10];
    const float* bj   = (const float*)d_in[11];
    const float* Wjs  = (const float*)d_in[12];
    const float* bjs  = (const float*)d_in[13];
    const float* Wp   = (const float*)d_in[14];
    const float* bp   = (const float*)d_in[15];
    const float* Ws   = (const float*)d_in[16];
    const float* bs   = (const float*)d_in[17];

    const int smem_s1 = XFB + WFB;     // 101376
    const int smem_e  = 3 * ESTG;      // 110592
    const int smem_s3 = XFB + WFB;     // 101376
    cudaFuncSetAttribute(stage1_kernel, cudaFuncAttributeMaxDynamicSharedMemorySize, smem_s1);
    cudaFuncSetAttribute(einsum_kernel, cudaFuncAttributeMaxDynamicSharedMemorySize, smem_e);
    cudaFuncSetAttribute(stage3_kernel, cudaFuncAttributeMaxDynamicSharedMemorySize, smem_s3);

    convert_w_kernel<<<6, 256>>>(Wis, Wi, Wjs, Wj, Ws, Wp);

    stage1_kernel<<<NN / 64, 256, smem_s1>>>(x2d, mask, ga1, be1,
                                             bi, bis, bj, bjs, bs);

    dim3 grid2(NDIM / 128, NDIM / 128, C);
    einsum_kernel<<<grid2, 256, smem_e>>>();

    stage3_kernel<<<NN / 64, 256, smem_s3>>>(mask, ga2, be2, bp, (float*)d_out);
}

// round 13
// speedup vs baseline: 1.6847x; 1.1439x over previous
#include <cuda_runtime.h>
#include <cuda_bf16.h>
#include <cstdint>
#include <math.h>

#define NDIM 512
#define C 128
#define NN (NDIM*NDIM)
#define PLANE NN
#define WFB 67584          // 128 x 132 f32 weight array bytes
#define XFB 33792          // 64 x 132 f32 activation array bytes
#define WCH 18432          // 128 n x 36 f32 (144 B) weight k-chunk bytes

// ---------------------------------------------------------------------------
// scratch
// ---------------------------------------------------------------------------
__device__ __align__(16) float g_i[(size_t)C*NN];     // tf32-rounded, channel-major
__device__ __align__(16) float g_j[(size_t)C*NN];
__device__ __align__(16) float g_ecm[(size_t)C*NN];
__device__ __align__(16) float g_sg [(size_t)NN*C];
__device__ __align__(16) float g_wf[6 * 128 * 128];   // tf32 [n][k]: Wis Wi Wjs Wj Ws Wp

extern __shared__ char smem_[];

// ---------------------------------------------------------------------------
// PTX helpers
// ---------------------------------------------------------------------------
__device__ __forceinline__ uint32_t smem_u32(const void* p) {
    uint32_t a;
    asm("{ .reg .u64 t; cvta.to.shared.u64 t, %1; cvt.u32.u64 %0, t; }" : "=r"(a) : "l"(p));
    return a;
}
__device__ __forceinline__ void ldm_x4(uint32_t addr, uint32_t* r) {
    asm volatile("ldmatrix.sync.aligned.m8n8.x4.shared.b16 {%0,%1,%2,%3}, [%4];"
        : "=r"(r[0]), "=r"(r[1]), "=r"(r[2]), "=r"(r[3]) : "r"(addr));
}
__device__ __forceinline__ void mma_tf32(float* d, const uint32_t* a, uint32_t b0, uint32_t b1) {
    asm volatile("mma.sync.aligned.m16n8k8.row.col.f32.tf32.tf32.f32 "
        "{%0,%1,%2,%3}, {%4,%5,%6,%7}, {%8,%9}, {%0,%1,%2,%3};"
        : "+f"(d[0]), "+f"(d[1]), "+f"(d[2]), "+f"(d[3])
        : "r"(a[0]), "r"(a[1]), "r"(a[2]), "r"(a[3]), "r"(b0), "r"(b1));
}
__device__ __forceinline__ void cp16(uint32_t dst, const void* src) {
    asm volatile("cp.async.cg.shared.global [%0], [%1], 16;" :: "r"(dst), "l"(src) : "memory");
}
#define CP_COMMIT() asm volatile("cp.async.commit_group;" ::: "memory")
#define CP_WAIT(n)  asm volatile("cp.async.wait_group %0;" :: "n"(n) : "memory")
__device__ __forceinline__ float sigmoidf_(float x) { return 1.0f / (1.0f + __expf(-x)); }
__device__ __forceinline__ float tf32r(float x) {
    float r;
    asm("cvt.rna.tf32.f32 %0, %1;" : "=f"(r) : "f"(x));
    return r;
}

// ---------------------------------------------------------------------------
// Prologue: transpose + tf32-round weights
// ---------------------------------------------------------------------------
__global__ void convert_w_kernel(const float* __restrict__ Wis, const float* __restrict__ Wi,
                                 const float* __restrict__ Wjs, const float* __restrict__ Wj,
                                 const float* __restrict__ Ws,  const float* __restrict__ Wp) {
    const float* src[6] = {Wis, Wi, Wjs, Wj, Ws, Wp};
    const float* W = src[blockIdx.x];
    float* outp = g_wf + (size_t)blockIdx.x * 16384;
    for (int idx = threadIdx.x; idx < 16384; idx += blockDim.x) {
        int n = idx >> 7, k = idx & 127;
        outp[n * 128 + k] = tf32r(W[k * 128 + n]);
    }
}

// cp.async one tf32 weight [128 n][132 f32 stride] into smem, 256 threads
__device__ __forceinline__ void loadWf(int m, uint32_t sW, int tid) {
    const char* src = (const char*)g_wf + (size_t)m * 65536;
    #pragma unroll
    for (int it = 0; it < 16; ++it) {
        int idx = tid + it * 256;
        int row = idx >> 5, ch = idx & 31;
        cp16(sW + row * 528 + ch * 16, src + row * 512 + ch * 16);
    }
}

// cp.async one weight k-chunk (chunk cc: weight cc>>2, kq cc&3) into ring buf
// dst layout: [128 n][144 B stride], 16384 data bytes. One commit group.
__device__ __forceinline__ void loadWchunk(int cc, uint32_t sRing, int tid) {
    int m = cc >> 2, kq = cc & 3;
    const char* src = (const char*)g_wf + (size_t)m * 65536 + kq * 128;
    uint32_t dst = sRing + (uint32_t)(cc & 3) * WCH;
    #pragma unroll
    for (int it = 0; it < 4; ++it) {
        int idx = tid + it * 256;
        int row = idx >> 3, ch = idx & 7;
        cp16(dst + row * 144 + ch * 16, src + (size_t)row * 512 + ch * 16);
    }
    CP_COMMIT();
}

// ---------------------------------------------------------------------------
// tf32 warp GEMM full-K (stage3): 32x32 warp tile, K=128, stride 528 B
// acc[(ma*4+na)*4+q]: q=0:(g,t2) 1:(g,t2+1) 2:(g+8,t2) 3:(g+8,t2+1)
// ---------------------------------------------------------------------------
__device__ __forceinline__ void wgemm_t32(uint32_t sA, uint32_t sB,
                                          int lane, int wm, int wn, float* acc) {
    int lr = lane & 7, sel = lane >> 3;
    uint32_t aRow = (uint32_t)((wm*32 + (sel & 1)*8 + lr) * 528 + (sel >> 1)*16);
    uint32_t bRow = (uint32_t)((wn*32 + (sel & 1)*8 + lr) * 528 + (sel >> 1)*16);
    #pragma unroll
    for (int kk = 0; kk < 16; ++kk) {
        uint32_t a[2][4];
        #pragma unroll
        for (int ma = 0; ma < 2; ++ma)
            ldm_x4(sA + aRow + (uint32_t)(ma * 16 * 528 + kk * 32), a[ma]);
        #pragma unroll
        for (int p = 0; p < 2; ++p) {
            uint32_t b[4];
            ldm_x4(sB + bRow + (uint32_t)(p * 16 * 528 + kk * 32), b);
            #pragma unroll
            for (int ma = 0; ma < 2; ++ma) {
                mma_tf32(acc + (ma*4 + p*2 + 0)*4, a[ma], b[0], b[2]);
                mma_tf32(acc + (ma*4 + p*2 + 1)*4, a[ma], b[1], b[3]);
            }
        }
    }
}

// k-chunk GEMM (stage1): A [64 r][528 B] at k-offset aOff, B chunk [128 n][144 B]
__device__ __forceinline__ void wgemm_chunk(uint32_t sA, uint32_t aOff, uint32_t sB,
                                            int lane, int wm, int wn, float* acc) {
    int lr = lane & 7, sel = lane >> 3;
    uint32_t aRow = (uint32_t)((wm*32 + (sel & 1)*8 + lr) * 528 + (sel >> 1)*16) + aOff;
    uint32_t bRow = (uint32_t)((wn*32 + (sel & 1)*8 + lr) * 144 + (sel >> 1)*16);
    #pragma unroll
    for (int kk = 0; kk < 4; ++kk) {
        uint32_t a[2][4];
        #pragma unroll
        for (int ma = 0; ma < 2; ++ma)
            ldm_x4(sA + aRow + (uint32_t)(ma * 16 * 528 + kk * 32), a[ma]);
        #pragma unroll
        for (int p = 0; p < 2; ++p) {
            uint32_t b[4];
            ldm_x4(sB + bRow + (uint32_t)(p * 16 * 144 + kk * 32), b);
            #pragma unroll
            for (int ma = 0; ma < 2; ++ma) {
                mma_tf32(acc + (ma*4 + p*2 + 0)*4, a[ma], b[0], b[2]);
                mma_tf32(acc + (ma*4 + p*2 + 1)*4, a[ma], b[1], b[3]);
            }
        }
    }
}

// ---------------------------------------------------------------------------
// Stage 1: LN + 5 GEMMs, 20-chunk 4-stage weight ring, 256 thr, 2 CTAs/SM.
// smem: Xf 64x132 f32 (33792) | ring 4x18432 (73728) = 107520 B
// Chunk cc -> weight cc>>2 (Wis Wi Wjs Wj Ws), k-quarter cc&3.
// PROC: wait(W) -> sync -> prefetch cc+3 -> mma chunk cc
// ---------------------------------------------------------------------------
#define S1_PROC(cc, ACC, W) do { \
    CP_WAIT(W); \
    __syncthreads(); \
    if ((cc) + 3 < 20) loadWchunk((cc) + 3, sRing, tid); \
    wgemm_chunk(sX, (uint32_t)(((cc) & 3) * 128), sRing + (uint32_t)((cc) & 3) * WCH, \
                lane, wm, wn, ACC); \
} while (0)

__global__ void __launch_bounds__(256, 2)
stage1_kernel(const float* __restrict__ x2d, const float* __restrict__ mask,
              const float* __restrict__ ga1, const float* __restrict__ be1,
              const float* __restrict__ bi,  const float* __restrict__ bis,
              const float* __restrict__ bj,  const float* __restrict__ bjs,
              const float* __restrict__ bs) {
    float* Xf = (float*)smem_;
    uint32_t sX = smem_u32(Xf);
    uint32_t sRing = sX + XFB;

    int tid = threadIdx.x, lane = tid & 31, w = tid >> 5;
    int wm = w >> 2, wn = w & 3;
    int g = lane >> 2, t2 = (lane & 3) * 2;
    size_t rowbase = (size_t)blockIdx.x * 64;

    loadWchunk(0, sRing, tid);
    loadWchunk(1, sRing, tid);
    loadWchunk(2, sRing, tid);

    // layernorm: 4 threads/row, 32 channels each
    {
        int r = tid >> 2, e = tid & 3;
        const float* xr = x2d + (rowbase + r) * C + e * 32;
        float v[32], s = 0.f, ss = 0.f;
        #pragma unroll
        for (int t = 0; t < 8; ++t) {
            float4 f = *(const float4*)(xr + t * 4);
            v[4*t+0]=f.x; v[4*t+1]=f.y; v[4*t+2]=f.z; v[4*t+3]=f.w;
            s += f.x + f.y + f.z + f.w;
            ss += f.x*f.x + f.y*f.y + f.z*f.z + f.w*f.w;
        }
        s  += __shfl_xor_sync(0xffffffffu, s, 1);
        s  += __shfl_xor_sync(0xffffffffu, s, 2);
        ss += __shfl_xor_sync(0xffffffffu, ss, 1);
        ss += __shfl_xor_sync(0xffffffffu, ss, 2);
        float mu = s * (1.0f / C);
        float rs = rsqrtf(ss * (1.0f / C) - mu * mu + 1e-5f);
        #pragma unroll
        for (int t = 0; t < 32; ++t) {
            int k = e * 32 + t;
            Xf[r * 132 + k] = tf32r((v[t] - mu) * rs * __ldg(ga1 + k) + __ldg(be1 + k));
        }
    }

    float accg[32], accm[32];

    #pragma unroll 1
    for (int pass = 0; pass < 2; ++pass) {
        const float* bgp = pass ? bjs : bis;
        const float* bmp = pass ? bj  : bi;
        float* outp = pass ? g_j : g_i;
        int base = pass * 8;

        // gate GEMM (4 chunks)
        #pragma unroll
        for (int q = 0; q < 32; ++q) accg[q] = 0.f;
        S1_PROC(base + 0, accg, 2);
        S1_PROC(base + 1, accg, 2);
        S1_PROC(base + 2, accg, 2);
        S1_PROC(base + 3, accg, 2);
        #pragma unroll
        for (int ma = 0; ma < 2; ++ma)
            #pragma unroll
            for (int na = 0; na < 4; ++na) {
                int idx = (ma*4 + na) * 4;
                int c0 = wn*32 + na*8 + t2;
                float b0 = __ldg(bgp + c0), b1 = __ldg(bgp + c0 + 1);
                accg[idx+0] = sigmoidf_(accg[idx+0] + b0);
                accg[idx+1] = sigmoidf_(accg[idx+1] + b1);
                accg[idx+2] = sigmoidf_(accg[idx+2] + b0);
                accg[idx+3] = sigmoidf_(accg[idx+3] + b1);
            }

        // main GEMM (4 chunks)
        #pragma unroll
        for (int q = 0; q < 32; ++q) accm[q] = 0.f;
        S1_PROC(base + 4, accm, 2);
        S1_PROC(base + 5, accm, 2);
        S1_PROC(base + 6, accm, 2);
        S1_PROC(base + 7, accm, 2);

        // epilogue: direct channel-major stores (sector-aligned scalar STG)
        #pragma unroll
        for (int ma = 0; ma < 2; ++ma) {
            int r0 = wm*32 + ma*16 + g;
            float m0 = __ldg(mask + rowbase + r0);
            float m1 = __ldg(mask + rowbase + r0 + 8);
            #pragma unroll
            for (int na = 0; na < 4; ++na) {
                int idx = (ma*4 + na) * 4;
                int c0 = wn*32 + na*8 + t2;
                float b0 = __ldg(bmp + c0), b1 = __ldg(bmp + c0 + 1);
                float* p0 = outp + (size_t)c0 * PLANE + rowbase + r0;
                float* p1 = outp + (size_t)(c0 + 1) * PLANE + rowbase + r0;
                p0[0] = tf32r((accm[idx+0] + b0) * accg[idx+0] * m0);
                p1[0] = tf32r((accm[idx+1] + b1) * accg[idx+1] * m0);
                p0[8] = tf32r((accm[idx+2] + b0) * accg[idx+2] * m1);
                p1[8] = tf32r((accm[idx+3] + b1) * accg[idx+3] * m1);
            }
        }
    }

    // sg = sigmoid(x@Ws+bs): chunks 16-19
    #pragma unroll
    for (int q = 0; q < 32; ++q) accg[q] = 0.f;
    S1_PROC(16, accg, 2);
    S1_PROC(17, accg, 2);
    S1_PROC(18, accg, 1);
    S1_PROC(19, accg, 0);
    #pragma unroll
    for (int ma = 0; ma < 2; ++ma) {
        size_t r0 = rowbase + wm*32 + ma*16 + g;
        #pragma unroll
        for (int na = 0; na < 4; ++na) {
            int idx = (ma*4 + na) * 4;
            int c0 = wn*32 + na*8 + t2;
            float b0 = __ldg(bs + c0), b1 = __ldg(bs + c0 + 1);
            *(float2*)(g_sg + r0 * C + c0) =
                make_float2(sigmoidf_(accg[idx+0] + b0), sigmoidf_(accg[idx+1] + b1));
            *(float2*)(g_sg + (r0 + 8) * C + c0) =
                make_float2(sigmoidf_(accg[idx+2] + b0), sigmoidf_(accg[idx+3] + b1));
        }
    }
}

// ---------------------------------------------------------------------------
// Stage 2: einsum, tf32, block 128x128, 256 threads, 2 CTAs/SM.
// 3-stage cp.async pipeline, ONE barrier per k-chunk. (R12)
// ---------------------------------------------------------------------------
#define ESTG 36864

__device__ __forceinline__ void e_load(uint32_t sdst,
                                       const char* pA, const char* pB,
                                       int kb, int tid) {
    #pragma unroll
    for (int it = 0; it < 4; ++it) {
        int idx = tid + it * 256;
        int row = idx >> 3, ch = idx & 7;
        cp16(sdst + row * 144 + ch * 16,
             pA + (size_t)row * 2048 + kb * 128 + ch * 16);
    }
    #pragma unroll
    for (int it = 0; it < 4; ++it) {
        int idx = tid + it * 256;
        int row = idx >> 3, ch = idx & 7;
        cp16(sdst + 18432 + row * 144 + ch * 16,
             pB + (size_t)row * 2048 + kb * 128 + ch * 16);
    }
}

__device__ __forceinline__ void e_mma(uint32_t st, int lane, int wm, int wn, float* acc) {
    int lr = lane & 7, sel = lane >> 3;
    uint32_t aRow = (uint32_t)((wm*32 + (sel & 1)*8 + lr) * 144 + (sel >> 1)*16);
    uint32_t bRow = (uint32_t)((wn*64 + (sel & 1)*8 + lr) * 144 + (sel >> 1)*16);
    uint32_t sA = st, sB = st + 18432;
    #pragma unroll
    for (int kk = 0; kk < 4; ++kk) {
        uint32_t a[2][4];
        #pragma unroll
        for (int ma = 0; ma < 2; ++ma)
            ldm_x4(sA + aRow + (uint32_t)(ma * 16 * 144 + kk * 32), a[ma]);
        #pragma unroll
        for (int p = 0; p < 4; ++p) {
            uint32_t b[4];
            ldm_x4(sB + bRow + (uint32_t)(p * 16 * 144 + kk * 32), b);
            #pragma unroll
            for (int ma = 0; ma < 2; ++ma) {
                mma_tf32(acc + (ma*8 + p*2 + 0)*4, a[ma], b[0], b[2]);
                mma_tf32(acc + (ma*8 + p*2 + 1)*4, a[ma], b[1], b[3]);
            }
        }
    }
}

__global__ void __launch_bounds__(256, 2)
einsum_kernel() {
    uint32_t sb = smem_u32(smem_);
    int tid = threadIdx.x, lane = tid & 31, w = tid >> 5;
    int wm = w >> 1, wn = w & 1;
    int g = lane >> 2, t2 = (lane & 3) * 2;
    int c = blockIdx.z;
    int ibase = blockIdx.x * 128, jbase = blockIdx.y * 128;

    const char* pA = (const char*)(g_i + (size_t)c * PLANE + (size_t)ibase * NDIM);
    const char* pB = (const char*)(g_j + (size_t)c * PLANE + (size_t)jbase * NDIM);

    float acc[64];
    #pragma unroll
    for (int q = 0; q < 64; ++q) acc[q] = 0.f;

    e_load(sb,        pA, pB, 0, tid); CP_COMMIT();
    e_load(sb + ESTG, pA, pB, 1, tid); CP_COMMIT();

    #pragma unroll 1
    for (int kb = 0; kb < 16; ++kb) {
        if (kb < 15) { CP_WAIT(1); } else { CP_WAIT(0); }
        __syncthreads();
        if (kb + 2 < 16) {
            e_load(sb + ((kb + 2) % 3) * ESTG, pA, pB, kb + 2, tid);
            CP_COMMIT();
        }
        e_mma(sb + (kb % 3) * ESTG, lane, wm, wn, acc);
    }

    float* O = g_ecm + (size_t)c * PLANE;
    #pragma unroll
    for (int ma = 0; ma < 2; ++ma) {
        size_t r0 = (size_t)(ibase + wm*32 + ma*16 + g);
        #pragma unroll
        for (int na = 0; na < 8; ++na) {
            int idx = (ma*8 + na) * 4;
            int c0 = jbase + wn*64 + na*8 + t2;
            *(float2*)(O + r0 * NDIM + c0)       = make_float2(acc[idx+0], acc[idx+1]);
            *(float2*)(O + (r0 + 8) * NDIM + c0) = make_float2(acc[idx+2], acc[idx+3]);
        }
    }
}

// ---------------------------------------------------------------------------
// Stage 3: 64-row tiles, 256 threads, 2 CTAs/SM. (R10/R12)
// smem: XT 64x132 f32 (33792) | W (67584) = 101376 B
// ---------------------------------------------------------------------------
__global__ void __launch_bounds__(256, 2)
stage3_kernel(const float* __restrict__ mask,
              const float* __restrict__ ga2, const float* __restrict__ be2,
              const float* __restrict__ bp,  float* __restrict__ out) {
    float* XT = (float*)smem_;
    uint32_t sXT = smem_u32(XT);
    uint32_t sW  = sXT + XFB;

    int tid = threadIdx.x, lane = tid & 31, w = tid >> 5;
    int wm = w >> 2, wn = w & 3;
    int g = lane >> 2, t2 = (lane & 3) * 2;
    size_t rowbase = (size_t)blockIdx.x * 64;

    loadWf(5, sW, tid);
    CP_COMMIT();

    // gather channel-major einsum output + LN over channels
    {
        int r = tid >> 2, e = tid & 3;
        const float* base = g_ecm + (size_t)(e * 32) * PLANE + rowbase + r;
        float v[32], s = 0.f, ss = 0.f;
        #pragma unroll
        for (int t = 0; t < 32; ++t) {
            float x = __ldg(base + (size_t)t * PLANE);
            v[t] = x; s += x; ss += x * x;
        }
        s  += __shfl_xor_sync(0xffffffffu, s, 1);
        s  += __shfl_xor_sync(0xffffffffu, s, 2);
        ss += __shfl_xor_sync(0xffffffffu, ss, 1);
        ss += __shfl_xor_sync(0xffffffffu, ss, 2);
        float mu = s * (1.0f / C);
        float rs = rsqrtf(ss * (1.0f / C) - mu * mu + 1e-5f);
        #pragma unroll
        for (int t = 0; t < 32; ++t) {
            int k = e * 32 + t;
            XT[r * 132 + k] = tf32r((v[t] - mu) * rs * __ldg(ga2 + k) + __ldg(be2 + k));
        }
    }
    CP_WAIT(0);
    __syncthreads();

    float acc[32];
    #pragma unroll
    for (int q = 0; q < 32; ++q) acc[q] = 0.f;
    wgemm_t32(sXT, sW, lane, wm, wn, acc);

    #pragma unroll
    for (int ma = 0; ma < 2; ++ma) {
        size_t r0 = rowbase + wm*32 + ma*16 + g;
        float m0 = __ldg(mask + r0);
        float m1 = __ldg(mask + r0 + 8);
        #pragma unroll
        for (int na = 0; na < 4; ++na) {
            int idx = (ma*4 + na) * 4;
            int c0 = wn*32 + na*8 + t2;
            float b0 = __ldg(bp + c0), b1 = __ldg(bp + c0 + 1);
            float2 s0 = *(const float2*)(g_sg + r0 * C + c0);
            float2 s1 = *(const float2*)(g_sg + (r0 + 8) * C + c0);
            *(float2*)(out + r0 * C + c0) =
                make_float2((acc[idx+0] + b0) * s0.x * m0, (acc[idx+1] + b1) * s0.y * m0);
            *(float2*)(out + (r0 + 8) * C + c0) =
                make_float2((acc[idx+2] + b0) * s1.x * m1, (acc[idx+3] + b1) * s1.y * m1);
        }
    }
}

// ---------------------------------------------------------------------------
extern "C" void kernel_launch(void* const* d_in, const int* in_sizes, int n_in,
                              void* d_out, int out_size) {
    const float* x2d  = (const float*)d_in[0];
    const float* mask = (const float*)d_in[1];
    const float* ga1  = (const float*)d_in[2];
    const float* be1  = (const float*)d_in[3];
    const float* ga2  = (const float*)d_in[4];
    const float* be2  = (const float*)d_in[5];
    const float* Wi   = (const float*)d_in[6];
    const float* bi   = (const float*)d_in[7];
    const float* Wis  = (const float*)d_in[8];
    const float* bis  = (const float*)d_in[9];
    const float* Wj   = (const float*)d_in[10];
    const float* bj   = (const float*)d_in[11];
    const float* Wjs  = (const float*)d_in[12];
    const float* bjs  = (const float*)d_in[13];
    const float* Wp   = (const float*)d_in[14];
    const float* bp   = (const float*)d_in[15];
    const float* Ws   = (const float*)d_in[16];
    const float* bs   = (const float*)d_in[17];

    const int smem_s1 = XFB + 4 * WCH;  // 107520
    const int smem_e  = 3 * ESTG;       // 110592
    const int smem_s3 = XFB + WFB;      // 101376
    cudaFuncSetAttribute(stage1_kernel, cudaFuncAttributeMaxDynamicSharedMemorySize, smem_s1);
    cudaFuncSetAttribute(einsum_kernel, cudaFuncAttributeMaxDynamicSharedMemorySize, smem_e);
    cudaFuncSetAttribute(stage3_kernel, cudaFuncAttributeMaxDynamicSharedMemorySize, smem_s3);

    convert_w_kernel<<<6, 256>>>(Wis, Wi, Wjs, Wj, Ws, Wp);

    stage1_kernel<<<NN / 64, 256, smem_s1>>>(x2d, mask, ga1, be1,
                                             bi, bis, bj, bjs, bs);

    dim3 grid2(NDIM / 128, NDIM / 128, C);
    einsum_kernel<<<grid2, 256, smem_e>>>();

    stage3_kernel<<<NN / 64, 256, smem_s3>>>(mask, ga2, be2, bp, (float*)d_out);
}